// round 2
// baseline (speedup 1.0000x reference)
#include <cuda_runtime.h>
#include <cuda_fp16.h>
#include <math.h>

// ---------------- problem constants ----------------
#define LDIM   65536
#define ST     100      // STATE
#define ST2    200      // 2*STATE
#define ATTD   100      // ATTENTION
#define EMBD   100
#define VOCABD 128
#define TSTEPS 258
#define GATES  400      // 4*STATE
#define MAXNB  160
#define CHMAX  1024     // max chunk length per block (NB >= 64)

// ---------------- device scratch (static, no allocs) ----------------
__device__ __half g_w1dt[(size_t)LDIM * ATTD];     // [l][j]  fp16, 13.1 MB
__device__ __half g_inT [(size_t)LDIM * ST2];      // [l][k]  fp16, 26.2 MB
__device__ float  g_embproj[VOCABD * GATES];       // b_ih+b_hh+W_ihE@emb[v]
__device__ __half g_WcT[ST2 * GATES];              // [k][r] = W_ih[r][k], k<200
__device__ __half g_WhT[ST  * GATES];              // [k][r] = W_hh[r][k]
__device__ __half g_w2T[ST2 * ATTD];               // [k][j] = w2[j][k]
__device__ __half g_linT[ST * VOCABD];             // [k][v] = lin_w[v][k]
__device__ float  g_w2dt[ATTD];
__device__ float  g_m[MAXNB];
__device__ float  g_s[MAXNB];
__device__ float  g_ctx[(size_t)MAXNB * ST2];
__device__ int    g_flags[MAXNB];
__device__ int    g_release;

// ---------------- helpers ----------------
__device__ __forceinline__ float tanh_fast(float x) {
    float y; asm("tanh.approx.f32 %0, %1;" : "=f"(y) : "f"(x)); return y;
}
__device__ __forceinline__ float sigmoidf(float x) { return 1.f / (1.f + __expf(-x)); }

// ---------------- kernel: reset sync state (runs each replay, before main) ----
__global__ void k_init_sync() {
    int t = blockIdx.x * blockDim.x + threadIdx.x;
    if (t < MAXNB) g_flags[t] = 0;
    if (t == 0) g_release = 0;
}

// ---------------- kernel: small weight prep (fp16 transposes + embproj) ------
__global__ void k_prep(const float* __restrict__ W_ih, const float* __restrict__ W_hh,
                       const float* __restrict__ b_ih, const float* __restrict__ b_hh,
                       const float* __restrict__ w2,   const float* __restrict__ lin_w,
                       const float* __restrict__ emb) {
    int gt = blockIdx.x * blockDim.x + threadIdx.x;
    int stride = gridDim.x * blockDim.x;
    for (int i = gt; i < GATES * ST2; i += stride) {
        int r = i / ST2, k = i % ST2;
        g_WcT[k * GATES + r] = __float2half(W_ih[r * 300 + k]);
    }
    for (int i = gt; i < GATES * ST; i += stride) {
        int r = i / ST, k = i % ST;
        g_WhT[k * GATES + r] = __float2half(W_hh[r * ST + k]);
    }
    for (int i = gt; i < ATTD * ST2; i += stride) {
        int j = i / ST2, k = i % ST2;
        g_w2T[k * ATTD + j] = __float2half(w2[j * ST2 + k]);
    }
    for (int i = gt; i < VOCABD * ST; i += stride) {
        int v = i / ST, k = i % ST;
        g_linT[k * VOCABD + v] = __float2half(lin_w[v * ST + k]);
    }
    // embproj[v][r] = b_ih[r] + b_hh[r] + sum_e W_ih[r][200+e]*emb[v][e]
    for (int i = gt; i < VOCABD * GATES; i += stride) {
        int v = i % VOCABD, r = i / VOCABD;      // v-minor: W_ih row broadcast per warp
        float a = b_ih[r] + b_hh[r];
        const float* wrow = &W_ih[r * 300 + 200];
        const float* erow = &emb[v * EMBD];
        #pragma unroll 4
        for (int e = 0; e < EMBD; e++) a = fmaf(wrow[e], erow[e], a);
        g_embproj[v * GATES + r] = a;
    }
}

// ---------------- kernel: w1dt = input^T @ w1^T (fp16 out) + input transpose -
// block: 128 threads, each owns one l; grid = L/128 = 512
__global__ __launch_bounds__(128, 1)
void k_w1dt(const float* __restrict__ inp, const float* __restrict__ w1) {
    extern __shared__ float sm[];
    float*  w1s = sm;                          // [k*100+j] : 20000 floats (80 KB)
    __half* inS = (__half*)(sm + 20000);       // [128][210] halfs (53.8 KB)
    const int tid = threadIdx.x;
    const int l0 = blockIdx.x * 128;
    const int l = l0 + tid;

    for (int idx = tid; idx < ATTD * ST2; idx += 128) {
        int j = idx / ST2, k = idx % ST2;      // w1 is [100][200] row-major
        w1s[k * ATTD + j] = w1[idx];
    }
    __syncthreads();

    float acc[ATTD];
    #pragma unroll
    for (int j = 0; j < ATTD; j++) acc[j] = 0.f;

    for (int k = 0; k < ST2; k++) {
        float x = inp[(size_t)k * LDIM + l];   // coalesced
        inS[tid * 210 + k] = __float2half(x);
        const float* wr = &w1s[k * ATTD];
        #pragma unroll
        for (int j = 0; j < ATTD; j++) acc[j] = fmaf(x, wr[j], acc[j]);
    }
    __syncthreads();

    // coalesced write of transposed fp16 input
    for (int idx = tid; idx < 128 * ST2; idx += 128) {
        int r = idx / ST2, kk = idx % ST2;
        g_inT[(size_t)(l0 + r) * ST2 + kk] = inS[r * 210 + kk];
    }
    __syncthreads();
    // stash accumulators to smem (reuse w1s region; 128*105 = 13440 < 20000)
    #pragma unroll
    for (int j = 0; j < ATTD; j++) sm[tid * 105 + j] = acc[j];
    __syncthreads();
    for (int idx = tid; idx < 128 * ATTD; idx += 128) {
        int r = idx / ATTD, j = idx % ATTD;
        g_w1dt[(size_t)(l0 + r) * ATTD + j] = __float2half(sm[r * 105 + j]);
    }
}

// ---------------- persistent decoder kernel ----------------
__global__ __launch_bounds__(512, 1)
void k_decoder(const int* __restrict__ out_ids, const float* __restrict__ v_w,
               const float* __restrict__ v_b,   const float* __restrict__ lin_b,
               const int* __restrict__ eos_id,  float* __restrict__ out, int NB) {
    __shared__ float sv[ATTD], sw2[ATTD];
    __shared__ float sscores[CHMAX];
    __shared__ float sredA[34], sredB[34];
    __shared__ float sctx[2][ST2];
    __shared__ float sx[ST2];
    __shared__ float sgates[GATES];
    __shared__ float slog[VOCABD];
    __shared__ float sh[ST], sc[ST];
    __shared__ int   s_last;

    const int b = blockIdx.x, tid = threadIdx.x;
    const int bd = blockDim.x;
    const int wid = tid >> 5, lane = tid & 31, nwarp = bd >> 5;
    const int chunk = (LDIM + NB - 1) / NB;
    const int l0 = b * chunk;
    int nl = LDIM - l0; if (nl > chunk) nl = chunk; if (nl < 0) nl = 0;

    for (int i = tid; i < ATTD; i += bd) sv[i] = v_w[i];
    const float vb = v_b[0];
    float loss = 0.f;

    if (b == 0) {
        // ---- priming step: h=c=0, x = [0(200); emb[eos]] ----
        if (tid < ST) { sh[tid] = 0.f; sc[tid] = 0.f; }
        if (tid == 0) s_last = eos_id[0];
        __syncthreads();
        if (tid < GATES) sgates[tid] = g_embproj[s_last * GATES + tid];
        __syncthreads();
        if (tid < ST) {
            float gi = sigmoidf(sgates[tid]);
            float gg = tanhf(sgates[2 * ST + tid]);
            float go = sigmoidf(sgates[3 * ST + tid]);
            float c = gi * gg;                 // f*c_prev = 0
            float h = go * tanhf(c);
            sh[tid] = h; sc[tid] = c;
        }
        __syncthreads();
        if (tid < ATTD) {
            float a = 0.f;
            for (int k = 0; k < ST; k++) a = fmaf(__half2float(g_w2T[k * ATTD + tid]), sh[k], a);
            for (int k = 0; k < ST; k++) a = fmaf(__half2float(g_w2T[(ST + k) * ATTD + tid]), sc[k], a);
            g_w2dt[tid] = a;
        }
        __threadfence();
        __syncthreads();
        if (tid == 0) *((volatile int*)&g_release) = 1;
    }

    for (int t = 0; t < TSTEPS; t++) {
        // ---- wait for w2dt of this step ----
        if (tid == 0) { while (*((volatile int*)&g_release) < t + 1) __nanosleep(64); }
        __syncthreads();
        __threadfence();
        for (int i = tid; i < ATTD; i += bd) sw2[i] = __ldcg(&g_w2dt[i]);
        __syncthreads();

        // ---- phase 1: scores over this block's chunk (warp per l, 2 l / iter) ----
        const int j0 = 2 * lane;
        for (int li = 2 * wid; li < nl; li += 2 * nwarp) {
            const __half2* row0 = (const __half2*)(g_w1dt + (size_t)(l0 + li) * ATTD);
            __half2 p0 = row0[lane];
            float2 f0 = __half22float2(p0);
            float a = tanh_fast(f0.x + sw2[j0]) * sv[j0] + tanh_fast(f0.y + sw2[j0 + 1]) * sv[j0 + 1];
            if (lane < 18) {
                __half2 p1 = row0[32 + lane];
                float2 f1 = __half22float2(p1);
                int j1 = 64 + 2 * lane;
                a += tanh_fast(f1.x + sw2[j1]) * sv[j1] + tanh_fast(f1.y + sw2[j1 + 1]) * sv[j1 + 1];
            }
            const bool has2 = (li + 1 < nl);
            float aB = 0.f;
            if (has2) {
                const __half2* row1 = (const __half2*)(g_w1dt + (size_t)(l0 + li + 1) * ATTD);
                __half2 q0 = row1[lane];
                float2 g0 = __half22float2(q0);
                aB = tanh_fast(g0.x + sw2[j0]) * sv[j0] + tanh_fast(g0.y + sw2[j0 + 1]) * sv[j0 + 1];
                if (lane < 18) {
                    __half2 q1 = row1[32 + lane];
                    float2 g1 = __half22float2(q1);
                    int j1 = 64 + 2 * lane;
                    aB += tanh_fast(g1.x + sw2[j1]) * sv[j1] + tanh_fast(g1.y + sw2[j1 + 1]) * sv[j1 + 1];
                }
            }
            #pragma unroll
            for (int off = 16; off; off >>= 1) {
                a  += __shfl_xor_sync(0xffffffffu, a, off);
                aB += __shfl_xor_sync(0xffffffffu, aB, off);
            }
            if (lane == 0) {
                sscores[li] = a + vb;
                if (has2) sscores[li + 1] = aB + vb;
            }
        }
        __syncthreads();

        // ---- block max / exp / sum ----
        float m = -1e30f;
        for (int i = tid; i < nl; i += bd) m = fmaxf(m, sscores[i]);
        #pragma unroll
        for (int off = 16; off; off >>= 1) m = fmaxf(m, __shfl_xor_sync(0xffffffffu, m, off));
        if (lane == 0) sredA[wid] = m;
        __syncthreads();
        if (tid == 0) {
            float mm = sredA[0];
            for (int i = 1; i < nwarp; i++) mm = fmaxf(mm, sredA[i]);
            sredA[32] = mm;
        }
        __syncthreads();
        m = sredA[32];

        float ssum = 0.f;
        for (int i = tid; i < nl; i += bd) {
            float p = __expf(sscores[i] - m);
            sscores[i] = p;
            ssum += p;
        }
        #pragma unroll
        for (int off = 16; off; off >>= 1) ssum += __shfl_xor_sync(0xffffffffu, ssum, off);
        if (lane == 0) sredB[wid] = ssum;
        __syncthreads();
        if (tid == 0) {
            float s = 0.f;
            for (int i = 0; i < nwarp; i++) s += sredB[i];
            sredB[32] = s;
        }
        __syncthreads();
        const float bsum = sredB[32];

        // ---- context partial: 2 groups of 200 threads split the l range ----
        if (tid < 2 * ST2) {
            const int grp = tid / ST2;
            const int k = tid - grp * ST2;
            const int lmid = nl >> 1;
            const int ls = grp ? lmid : 0;
            const int le = grp ? nl : lmid;
            const __half* base = g_inT + (size_t)l0 * ST2 + k;
            float a0 = 0.f, a1 = 0.f, a2 = 0.f, a3 = 0.f;
            int li = ls;
            for (; li + 4 <= le; li += 4) {
                a0 = fmaf(sscores[li    ], __half2float(base[(size_t)(li    ) * ST2]), a0);
                a1 = fmaf(sscores[li + 1], __half2float(base[(size_t)(li + 1) * ST2]), a1);
                a2 = fmaf(sscores[li + 2], __half2float(base[(size_t)(li + 2) * ST2]), a2);
                a3 = fmaf(sscores[li + 3], __half2float(base[(size_t)(li + 3) * ST2]), a3);
            }
            for (; li < le; li++)
                a0 = fmaf(sscores[li], __half2float(base[(size_t)li * ST2]), a0);
            sctx[grp][k] = (a0 + a1) + (a2 + a3);
        }
        __syncthreads();
        if (tid < ST2)      g_ctx[(size_t)b * ST2 + tid] = sctx[0][tid] + sctx[1][tid];
        if (tid == ST2)     g_m[b] = m;
        if (tid == ST2 + 1) g_s[b] = bsum;
        __threadfence();
        __syncthreads();
        if (tid == 0) *((volatile int*)&g_flags[b]) = t + 1;

        // ---- block 0: merge partials, LSTM, logits, loss, next w2dt ----
        if (b == 0) {
            if (tid < NB) { while (*((volatile int*)&g_flags[tid]) < t + 1) __nanosleep(32); }
            __syncthreads();
            __threadfence();

            float mi = (tid < NB) ? __ldcg(&g_m[tid]) : -1e30f;
            float M = mi;
            #pragma unroll
            for (int off = 16; off; off >>= 1) M = fmaxf(M, __shfl_xor_sync(0xffffffffu, M, off));
            if (lane == 0) sredA[wid] = M;
            __syncthreads();
            if (tid == 0) {
                float mm = sredA[0];
                for (int i = 1; i < nwarp; i++) mm = fmaxf(mm, sredA[i]);
                sredA[32] = mm;
            }
            __syncthreads();
            M = sredA[32];

            float si  = (tid < NB) ? __ldcg(&g_s[tid]) : 0.f;
            float scl = (tid < NB) ? __expf(mi - M) : 0.f;
            if (tid < NB) sscores[tid] = scl;          // reuse as scale buffer
            float contrib = si * scl;
            #pragma unroll
            for (int off = 16; off; off >>= 1) contrib += __shfl_xor_sync(0xffffffffu, contrib, off);
            if (lane == 0) sredB[wid] = contrib;
            __syncthreads();
            if (tid == 0) {
                float s = 0.f;
                for (int i = 0; i < nwarp; i++) s += sredB[i];
                sredB[32] = s;
            }
            __syncthreads();
            const float Sinv = 1.f / sredB[32];

            if (tid < ST2) {
                float a = 0.f;
                for (int i = 0; i < NB; i++)
                    a = fmaf(__ldcg(&g_ctx[(size_t)i * ST2 + tid]), sscores[i], a);
                sx[tid] = a * Sinv;
            }
            __syncthreads();

            if (tid < GATES) {
                float a = g_embproj[s_last * GATES + tid];
                #pragma unroll 4
                for (int k = 0; k < ST2; k++) a = fmaf(__half2float(g_WcT[k * GATES + tid]), sx[k], a);
                #pragma unroll 4
                for (int k = 0; k < ST;  k++) a = fmaf(__half2float(g_WhT[k * GATES + tid]), sh[k], a);
                sgates[tid] = a;
            }
            __syncthreads();
            if (tid < ST) {
                float gi = sigmoidf(sgates[tid]);
                float gf = sigmoidf(sgates[ST + tid]);
                float gg = tanhf(sgates[2 * ST + tid]);
                float go = sigmoidf(sgates[3 * ST + tid]);
                float c = gf * sc[tid] + gi * gg;
                float h = go * tanhf(c);
                sc[tid] = c; sh[tid] = h;
            }
            __syncthreads();
            if (tid < VOCABD) {
                float a = lin_b[tid];
                #pragma unroll 4
                for (int k = 0; k < ST; k++) a = fmaf(__half2float(g_linT[k * VOCABD + tid]), sh[k], a);
                slog[tid] = a;
            }
            __syncthreads();
            // log-sum-exp over 128 logits (4 warps)
            if (tid < VOCABD) {
                float v = slog[tid];
                #pragma unroll
                for (int off = 16; off; off >>= 1) v = fmaxf(v, __shfl_xor_sync(0xffffffffu, v, off));
                if (lane == 0) sredA[wid] = v;
            }
            __syncthreads();
            if (tid == 0)
                sredA[32] = fmaxf(fmaxf(sredA[0], sredA[1]), fmaxf(sredA[2], sredA[3]));
            __syncthreads();
            if (tid < VOCABD) {
                float e = __expf(slog[tid] - sredA[32]);
                #pragma unroll
                for (int off = 16; off; off >>= 1) e += __shfl_xor_sync(0xffffffffu, e, off);
                if (lane == 0) sredB[wid] = e;
            }
            __syncthreads();
            if (tid == 0) {
                float S2 = sredB[0] + sredB[1] + sredB[2] + sredB[3];
                int ch = out_ids[t];
                loss += (sredA[32] + logf(S2)) - slog[ch];
                s_last = ch;
            }
            __syncthreads();
            // next step's w2dt
            if (tid < ATTD) {
                float a = 0.f;
                for (int k = 0; k < ST; k++) a = fmaf(__half2float(g_w2T[k * ATTD + tid]), sh[k], a);
                for (int k = 0; k < ST; k++) a = fmaf(__half2float(g_w2T[(ST + k) * ATTD + tid]), sc[k], a);
                g_w2dt[tid] = a;
            }
            __threadfence();
            __syncthreads();
            if (tid == 0) *((volatile int*)&g_release) = t + 2;
        }
    }
    if (b == 0 && tid == 0) out[0] = loss;
}

// ---------------- launch ----------------
extern "C" void kernel_launch(void* const* d_in, const int* in_sizes, int n_in,
                              void* d_out, int out_size) {
    const float* input_mat = (const float*)d_in[0];
    const int*   out_ids   = (const int*)  d_in[1];
    const float* W_ih      = (const float*)d_in[2];
    const float* W_hh      = (const float*)d_in[3];
    const float* b_ih      = (const float*)d_in[4];
    const float* b_hh      = (const float*)d_in[5];
    const float* w1        = (const float*)d_in[6];
    const float* w2        = (const float*)d_in[7];
    const float* v_w       = (const float*)d_in[8];
    const float* v_b       = (const float*)d_in[9];
    const float* lin_w     = (const float*)d_in[10];
    const float* lin_b     = (const float*)d_in[11];
    const float* emb       = (const float*)d_in[12];
    const int*   eos_id    = (const int*)  d_in[13];
    float* out = (float*)d_out;

    int nb = 148;
    cudaDeviceGetAttribute(&nb, cudaDevAttrMultiProcessorCount, 0);
    if (nb > MAXNB) nb = MAXNB;
    if (nb < 64) nb = 64;   // keep chunk <= CHMAX

    static const size_t smemA = 20000 * sizeof(float) + 128 * 210 * sizeof(__half);
    cudaFuncSetAttribute(k_w1dt, cudaFuncAttributeMaxDynamicSharedMemorySize, (int)smemA);

    k_init_sync<<<1, 256>>>();
    k_prep<<<80, 256>>>(W_ih, W_hh, b_ih, b_hh, w2, lin_w, emb);
    k_w1dt<<<LDIM / 128, 128, smemA>>>(input_mat, w1);
    k_decoder<<<nb, 512>>>(out_ids, v_w, v_b, lin_b, eos_id, out, nb);
}

// round 3
// speedup vs baseline: 1.0043x; 1.0043x over previous
#include <cuda_runtime.h>
#include <cuda_fp16.h>
#include <math.h>

// ---------------- problem constants ----------------
#define LDIM   65536
#define ST     100      // STATE
#define ST2    200      // 2*STATE
#define ATTD   100      // ATTENTION
#define EMBD   100
#define VOCABD 128
#define TSTEPS 258
#define GATES  400      // 4*STATE
#define MAXNB  160
#define CHMAX  1024     // max chunk length per block (NB >= 64)

// ---------------- device scratch (static, no allocs) ----------------
__device__ __half g_w1dt[(size_t)LDIM * ATTD];     // [l][j]  fp16, 13.1 MB
__device__ __half g_inT [(size_t)LDIM * ST2];      // [l][k]  fp16, 26.2 MB
__device__ float  g_embproj[VOCABD * GATES];       // b_ih+b_hh+W_ihE@emb[v]
__device__ __half g_WcT[ST2 * GATES];              // [k][r] = W_ih[r][k], k<200
__device__ __half g_WhT[ST  * GATES];              // [k][r] = W_hh[r][k]
__device__ __half g_w2T[ST2 * ATTD];               // [k][j] = w2[j][k]
__device__ __half g_linT[ST * VOCABD];             // [k][v] = lin_w[v][k]
__device__ float  g_w2dt[ATTD];
__device__ float  g_m[MAXNB];
__device__ float  g_s[MAXNB];
__device__ float  g_ctx[(size_t)MAXNB * ST2];
__device__ int    g_flags[MAXNB];
__device__ int    g_release;

// ---------------- helpers ----------------
__device__ __forceinline__ float tanh_fast(float x) {
    float y; asm("tanh.approx.f32 %0, %1;" : "=f"(y) : "f"(x)); return y;
}
__device__ __forceinline__ float sigmoidf(float x) { return 1.f / (1.f + __expf(-x)); }

// ---------------- kernel: reset sync state (runs each replay, before main) ----
__global__ void k_init_sync() {
    int t = blockIdx.x * blockDim.x + threadIdx.x;
    if (t < MAXNB) g_flags[t] = 0;
    if (t == 0) g_release = 0;
}

// ---------------- kernel: small weight prep (fp16 transposes + embproj) ------
__global__ void k_prep(const float* __restrict__ W_ih, const float* __restrict__ W_hh,
                       const float* __restrict__ b_ih, const float* __restrict__ b_hh,
                       const float* __restrict__ w2,   const float* __restrict__ lin_w,
                       const float* __restrict__ emb) {
    int gt = blockIdx.x * blockDim.x + threadIdx.x;
    int stride = gridDim.x * blockDim.x;
    for (int i = gt; i < GATES * ST2; i += stride) {
        int r = i / ST2, k = i % ST2;
        g_WcT[k * GATES + r] = __float2half(W_ih[r * 300 + k]);
    }
    for (int i = gt; i < GATES * ST; i += stride) {
        int r = i / ST, k = i % ST;
        g_WhT[k * GATES + r] = __float2half(W_hh[r * ST + k]);
    }
    for (int i = gt; i < ATTD * ST2; i += stride) {
        int j = i / ST2, k = i % ST2;
        g_w2T[k * ATTD + j] = __float2half(w2[j * ST2 + k]);
    }
    for (int i = gt; i < VOCABD * ST; i += stride) {
        int v = i / ST, k = i % ST;
        g_linT[k * VOCABD + v] = __float2half(lin_w[v * ST + k]);
    }
    // embproj[v][r] = b_ih[r] + b_hh[r] + sum_e W_ih[r][200+e]*emb[v][e]
    for (int i = gt; i < VOCABD * GATES; i += stride) {
        int v = i % VOCABD, r = i / VOCABD;      // v-minor: W_ih row broadcast per warp
        float a = b_ih[r] + b_hh[r];
        const float* wrow = &W_ih[r * 300 + 200];
        const float* erow = &emb[v * EMBD];
        #pragma unroll 4
        for (int e = 0; e < EMBD; e++) a = fmaf(wrow[e], erow[e], a);
        g_embproj[v * GATES + r] = a;
    }
}

// ---------------- kernel: w1dt = input^T @ w1^T (fp16 out) + input transpose -
// block: 128 threads, each owns one l; grid = L/128 = 512
__global__ __launch_bounds__(128, 1)
void k_w1dt(const float* __restrict__ inp, const float* __restrict__ w1) {
    extern __shared__ float sm[];
    float*  w1s = sm;                          // [k*100+j] : 20000 floats (80 KB)
    __half* inS = (__half*)(sm + 20000);       // [128][210] halfs (53.8 KB)
    const int tid = threadIdx.x;
    const int l0 = blockIdx.x * 128;
    const int l = l0 + tid;

    for (int idx = tid; idx < ATTD * ST2; idx += 128) {
        int j = idx / ST2, k = idx % ST2;      // w1 is [100][200] row-major
        w1s[k * ATTD + j] = w1[idx];
    }
    __syncthreads();

    float acc[ATTD];
    #pragma unroll
    for (int j = 0; j < ATTD; j++) acc[j] = 0.f;

    for (int k = 0; k < ST2; k++) {
        float x = inp[(size_t)k * LDIM + l];   // coalesced
        inS[tid * 210 + k] = __float2half(x);
        const float* wr = &w1s[k * ATTD];
        #pragma unroll
        for (int j = 0; j < ATTD; j++) acc[j] = fmaf(x, wr[j], acc[j]);
    }
    __syncthreads();

    // coalesced write of transposed fp16 input
    for (int idx = tid; idx < 128 * ST2; idx += 128) {
        int r = idx / ST2, kk = idx % ST2;
        g_inT[(size_t)(l0 + r) * ST2 + kk] = inS[r * 210 + kk];
    }
    __syncthreads();
    // stash accumulators to smem (reuse w1s region; 128*105 = 13440 < 20000)
    #pragma unroll
    for (int j = 0; j < ATTD; j++) sm[tid * 105 + j] = acc[j];
    __syncthreads();
    for (int idx = tid; idx < 128 * ATTD; idx += 128) {
        int r = idx / ATTD, j = idx % ATTD;
        g_w1dt[(size_t)(l0 + r) * ATTD + j] = __float2half(sm[r * 105 + j]);
    }
}

// ---------------- persistent decoder kernel ----------------
__global__ __launch_bounds__(512, 1)
void k_decoder(const int* __restrict__ out_ids, const float* __restrict__ v_w,
               const float* __restrict__ v_b,   const float* __restrict__ lin_b,
               const int* __restrict__ eos_id,  float* __restrict__ out, int NB) {
    __shared__ float sv[ATTD], sw2[ATTD];
    __shared__ float sscores[CHMAX];
    __shared__ float sredA[34], sredB[34];
    __shared__ float sctx[2][ST2];
    __shared__ float sx[ST2];
    __shared__ float sgates[GATES];
    __shared__ float slog[VOCABD];
    __shared__ float sh[ST], sc[ST];
    __shared__ int   s_last;

    const int b = blockIdx.x, tid = threadIdx.x;
    const int bd = blockDim.x;
    const int wid = tid >> 5, lane = tid & 31, nwarp = bd >> 5;
    const int chunk = (LDIM + NB - 1) / NB;
    const int l0 = b * chunk;
    int nl = LDIM - l0; if (nl > chunk) nl = chunk; if (nl < 0) nl = 0;

    for (int i = tid; i < ATTD; i += bd) sv[i] = v_w[i];
    const float vb = v_b[0];
    float loss = 0.f;

    if (b == 0) {
        // ---- priming step: h=c=0, x = [0(200); emb[eos]] ----
        if (tid < ST) { sh[tid] = 0.f; sc[tid] = 0.f; }
        if (tid == 0) s_last = eos_id[0];
        __syncthreads();
        if (tid < GATES) sgates[tid] = g_embproj[s_last * GATES + tid];
        __syncthreads();
        if (tid < ST) {
            float gi = sigmoidf(sgates[tid]);
            float gg = tanhf(sgates[2 * ST + tid]);
            float go = sigmoidf(sgates[3 * ST + tid]);
            float c = gi * gg;                 // f*c_prev = 0
            float h = go * tanhf(c);
            sh[tid] = h; sc[tid] = c;
        }
        __syncthreads();
        if (tid < ATTD) {
            float a = 0.f;
            for (int k = 0; k < ST; k++) a = fmaf(__half2float(g_w2T[k * ATTD + tid]), sh[k], a);
            for (int k = 0; k < ST; k++) a = fmaf(__half2float(g_w2T[(ST + k) * ATTD + tid]), sc[k], a);
            g_w2dt[tid] = a;
        }
        __threadfence();
        __syncthreads();
        if (tid == 0) *((volatile int*)&g_release) = 1;
    }

    for (int t = 0; t < TSTEPS; t++) {
        // ---- wait for w2dt of this step ----
        if (tid == 0) { while (*((volatile int*)&g_release) < t + 1) __nanosleep(64); }
        __syncthreads();
        __threadfence();
        for (int i = tid; i < ATTD; i += bd) sw2[i] = __ldcg(&g_w2dt[i]);
        __syncthreads();

        // ---- phase 1: scores over this block's chunk (warp per l, 2 l / iter) ----
        const int j0 = 2 * lane;
        for (int li = 2 * wid; li < nl; li += 2 * nwarp) {
            const __half2* row0 = (const __half2*)(g_w1dt + (size_t)(l0 + li) * ATTD);
            __half2 p0 = row0[lane];
            float2 f0 = __half22float2(p0);
            float a = tanh_fast(f0.x + sw2[j0]) * sv[j0] + tanh_fast(f0.y + sw2[j0 + 1]) * sv[j0 + 1];
            if (lane < 18) {
                __half2 p1 = row0[32 + lane];
                float2 f1 = __half22float2(p1);
                int j1 = 64 + 2 * lane;
                a += tanh_fast(f1.x + sw2[j1]) * sv[j1] + tanh_fast(f1.y + sw2[j1 + 1]) * sv[j1 + 1];
            }
            const bool has2 = (li + 1 < nl);
            float aB = 0.f;
            if (has2) {
                const __half2* row1 = (const __half2*)(g_w1dt + (size_t)(l0 + li + 1) * ATTD);
                __half2 q0 = row1[lane];
                float2 g0 = __half22float2(q0);
                aB = tanh_fast(g0.x + sw2[j0]) * sv[j0] + tanh_fast(g0.y + sw2[j0 + 1]) * sv[j0 + 1];
                if (lane < 18) {
                    __half2 q1 = row1[32 + lane];
                    float2 g1 = __half22float2(q1);
                    int j1 = 64 + 2 * lane;
                    aB += tanh_fast(g1.x + sw2[j1]) * sv[j1] + tanh_fast(g1.y + sw2[j1 + 1]) * sv[j1 + 1];
                }
            }
            #pragma unroll
            for (int off = 16; off; off >>= 1) {
                a  += __shfl_xor_sync(0xffffffffu, a, off);
                aB += __shfl_xor_sync(0xffffffffu, aB, off);
            }
            if (lane == 0) {
                sscores[li] = a + vb;
                if (has2) sscores[li + 1] = aB + vb;
            }
        }
        __syncthreads();

        // ---- block max / exp / sum ----
        float m = -1e30f;
        for (int i = tid; i < nl; i += bd) m = fmaxf(m, sscores[i]);
        #pragma unroll
        for (int off = 16; off; off >>= 1) m = fmaxf(m, __shfl_xor_sync(0xffffffffu, m, off));
        if (lane == 0) sredA[wid] = m;
        __syncthreads();
        if (tid == 0) {
            float mm = sredA[0];
            for (int i = 1; i < nwarp; i++) mm = fmaxf(mm, sredA[i]);
            sredA[32] = mm;
        }
        __syncthreads();
        m = sredA[32];

        float ssum = 0.f;
        for (int i = tid; i < nl; i += bd) {
            float p = __expf(sscores[i] - m);
            sscores[i] = p;
            ssum += p;
        }
        #pragma unroll
        for (int off = 16; off; off >>= 1) ssum += __shfl_xor_sync(0xffffffffu, ssum, off);
        if (lane == 0) sredB[wid] = ssum;
        __syncthreads();
        if (tid == 0) {
            float s = 0.f;
            for (int i = 0; i < nwarp; i++) s += sredB[i];
            sredB[32] = s;
        }
        __syncthreads();
        const float bsum = sredB[32];

        // ---- context partial: 2 groups of 200 threads split the l range ----
        if (tid < 2 * ST2) {
            const int grp = tid / ST2;
            const int k = tid - grp * ST2;
            const int lmid = nl >> 1;
            const int ls = grp ? lmid : 0;
            const int le = grp ? nl : lmid;
            const __half* base = g_inT + (size_t)l0 * ST2 + k;
            float a0 = 0.f, a1 = 0.f, a2 = 0.f, a3 = 0.f;
            int li = ls;
            for (; li + 4 <= le; li += 4) {
                a0 = fmaf(sscores[li    ], __half2float(base[(size_t)(li    ) * ST2]), a0);
                a1 = fmaf(sscores[li + 1], __half2float(base[(size_t)(li + 1) * ST2]), a1);
                a2 = fmaf(sscores[li + 2], __half2float(base[(size_t)(li + 2) * ST2]), a2);
                a3 = fmaf(sscores[li + 3], __half2float(base[(size_t)(li + 3) * ST2]), a3);
            }
            for (; li < le; li++)
                a0 = fmaf(sscores[li], __half2float(base[(size_t)li * ST2]), a0);
            sctx[grp][k] = (a0 + a1) + (a2 + a3);
        }
        __syncthreads();
        if (tid < ST2)      g_ctx[(size_t)b * ST2 + tid] = sctx[0][tid] + sctx[1][tid];
        if (tid == ST2)     g_m[b] = m;
        if (tid == ST2 + 1) g_s[b] = bsum;
        __threadfence();
        __syncthreads();
        if (tid == 0) *((volatile int*)&g_flags[b]) = t + 1;

        // ---- block 0: merge partials, LSTM, logits, loss, next w2dt ----
        if (b == 0) {
            if (tid < NB) { while (*((volatile int*)&g_flags[tid]) < t + 1) __nanosleep(32); }
            __syncthreads();
            __threadfence();

            float mi = (tid < NB) ? __ldcg(&g_m[tid]) : -1e30f;
            float M = mi;
            #pragma unroll
            for (int off = 16; off; off >>= 1) M = fmaxf(M, __shfl_xor_sync(0xffffffffu, M, off));
            if (lane == 0) sredA[wid] = M;
            __syncthreads();
            if (tid == 0) {
                float mm = sredA[0];
                for (int i = 1; i < nwarp; i++) mm = fmaxf(mm, sredA[i]);
                sredA[32] = mm;
            }
            __syncthreads();
            M = sredA[32];

            float si  = (tid < NB) ? __ldcg(&g_s[tid]) : 0.f;
            float scl = (tid < NB) ? __expf(mi - M) : 0.f;
            if (tid < NB) sscores[tid] = scl;          // reuse as scale buffer
            float contrib = si * scl;
            #pragma unroll
            for (int off = 16; off; off >>= 1) contrib += __shfl_xor_sync(0xffffffffu, contrib, off);
            if (lane == 0) sredB[wid] = contrib;
            __syncthreads();
            if (tid == 0) {
                float s = 0.f;
                for (int i = 0; i < nwarp; i++) s += sredB[i];
                sredB[32] = s;
            }
            __syncthreads();
            const float Sinv = 1.f / sredB[32];

            if (tid < ST2) {
                float a = 0.f;
                for (int i = 0; i < NB; i++)
                    a = fmaf(__ldcg(&g_ctx[(size_t)i * ST2 + tid]), sscores[i], a);
                sx[tid] = a * Sinv;
            }
            __syncthreads();

            if (tid < GATES) {
                float a = g_embproj[s_last * GATES + tid];
                #pragma unroll 4
                for (int k = 0; k < ST2; k++) a = fmaf(__half2float(g_WcT[k * GATES + tid]), sx[k], a);
                #pragma unroll 4
                for (int k = 0; k < ST;  k++) a = fmaf(__half2float(g_WhT[k * GATES + tid]), sh[k], a);
                sgates[tid] = a;
            }
            __syncthreads();
            if (tid < ST) {
                float gi = sigmoidf(sgates[tid]);
                float gf = sigmoidf(sgates[ST + tid]);
                float gg = tanhf(sgates[2 * ST + tid]);
                float go = sigmoidf(sgates[3 * ST + tid]);
                float c = gf * sc[tid] + gi * gg;
                float h = go * tanhf(c);
                sc[tid] = c; sh[tid] = h;
            }
            __syncthreads();
            if (tid < VOCABD) {
                float a = lin_b[tid];
                #pragma unroll 4
                for (int k = 0; k < ST; k++) a = fmaf(__half2float(g_linT[k * VOCABD + tid]), sh[k], a);
                slog[tid] = a;
            }
            __syncthreads();
            // log-sum-exp over 128 logits (4 warps)
            if (tid < VOCABD) {
                float v = slog[tid];
                #pragma unroll
                for (int off = 16; off; off >>= 1) v = fmaxf(v, __shfl_xor_sync(0xffffffffu, v, off));
                if (lane == 0) sredA[wid] = v;
            }
            __syncthreads();
            if (tid == 0)
                sredA[32] = fmaxf(fmaxf(sredA[0], sredA[1]), fmaxf(sredA[2], sredA[3]));
            __syncthreads();
            if (tid < VOCABD) {
                float e = __expf(slog[tid] - sredA[32]);
                #pragma unroll
                for (int off = 16; off; off >>= 1) e += __shfl_xor_sync(0xffffffffu, e, off);
                if (lane == 0) sredB[wid] = e;
            }
            __syncthreads();
            if (tid == 0) {
                float S2 = sredB[0] + sredB[1] + sredB[2] + sredB[3];
                int ch = out_ids[t];
                loss += (sredA[32] + logf(S2)) - slog[ch];
                s_last = ch;
            }
            __syncthreads();
            // next step's w2dt
            if (tid < ATTD) {
                float a = 0.f;
                for (int k = 0; k < ST; k++) a = fmaf(__half2float(g_w2T[k * ATTD + tid]), sh[k], a);
                for (int k = 0; k < ST; k++) a = fmaf(__half2float(g_w2T[(ST + k) * ATTD + tid]), sc[k], a);
                g_w2dt[tid] = a;
            }
            __threadfence();
            __syncthreads();
            if (tid == 0) *((volatile int*)&g_release) = t + 2;
        }
    }
    if (b == 0 && tid == 0) out[0] = loss;
}

// ---------------- launch ----------------
extern "C" void kernel_launch(void* const* d_in, const int* in_sizes, int n_in,
                              void* d_out, int out_size) {
    const float* input_mat = (const float*)d_in[0];
    const int*   out_ids   = (const int*)  d_in[1];
    const float* W_ih      = (const float*)d_in[2];
    const float* W_hh      = (const float*)d_in[3];
    const float* b_ih      = (const float*)d_in[4];
    const float* b_hh      = (const float*)d_in[5];
    const float* w1        = (const float*)d_in[6];
    const float* w2        = (const float*)d_in[7];
    const float* v_w       = (const float*)d_in[8];
    const float* v_b       = (const float*)d_in[9];
    const float* lin_w     = (const float*)d_in[10];
    const float* lin_b     = (const float*)d_in[11];
    const float* emb       = (const float*)d_in[12];
    const int*   eos_id    = (const int*)  d_in[13];
    float* out = (float*)d_out;

    int nb = 148;
    cudaDeviceGetAttribute(&nb, cudaDevAttrMultiProcessorCount, 0);
    if (nb > MAXNB) nb = MAXNB;
    if (nb < 64) nb = 64;   // keep chunk <= CHMAX

    static const size_t smemA = 20000 * sizeof(float) + 128 * 210 * sizeof(__half);
    cudaFuncSetAttribute(k_w1dt, cudaFuncAttributeMaxDynamicSharedMemorySize, (int)smemA);

    k_init_sync<<<1, 256>>>();
    k_prep<<<80, 256>>>(W_ih, W_hh, b_ih, b_hh, w2, lin_w, emb);
    k_w1dt<<<LDIM / 128, 128, smemA>>>(input_mat, w1);
    k_decoder<<<nb, 512>>>(out_ids, v_w, v_b, lin_b, eos_id, out, nb);
}

// round 5
// speedup vs baseline: 2.9419x; 2.9292x over previous
#include <cuda_runtime.h>
#include <cuda_fp16.h>
#include <math.h>

// ---------------- problem constants ----------------
#define LDIM   65536
#define ST     100
#define ST2    200
#define ATTD   100
#define EMBD   100
#define VOCABD 128
#define TSTEPS 258
#define GATES  400
#define MAXNB  160
#define CHMAX  1024

// ---------------- device scratch ----------------
__device__ __half2 g_w1dtT2[50ull * LDIM];          // [j2][l]   13.1 MB (j pair)
__device__ __half2 g_inT2[(size_t)LDIM * 100];      // [l][q]    26.2 MB (k pair)
__device__ float   g_embproj[VOCABD * GATES];       // [v][r]
__device__ uint2   g_WcQ[50 * GATES];               // [u][r] packs W_ih[r][4u..4u+3] (x part)
__device__ uint2   g_WhQ[25 * GATES];               // [u][r] packs W_hh[r][4u..4u+3]
__device__ uint2   g_w2Q[50 * ATTD];                // [u][j] packs w2[j][4u..4u+3]
__device__ uint2   g_linQ[25 * VOCABD];             // [u][v] packs lin_w[v][4u..4u+3]
__device__ float2  g_ctx[2][MAXNB * ATTD];          // parity-buffered partial ctx (k pairs)
__device__ float   g_s[2][MAXNB];                   // parity-buffered partial exp sums
__device__ float   g_h[TSTEPS][ST];
__device__ float   g_losspart[MAXNB];
__device__ int     g_arrive;

// ---------------- helpers ----------------
__device__ __forceinline__ float tanh_fast(float x) {
    float y; asm("tanh.approx.f32 %0, %1;" : "=f"(y) : "f"(x)); return y;
}
__device__ __forceinline__ float sigmoidf_(float x) { return 1.f / (1.f + __expf(-x)); }
__device__ __forceinline__ __half2 u2h2(unsigned u) {
    __half2 h; *reinterpret_cast<unsigned*>(&h) = u; return h;
}
__device__ __forceinline__ unsigned packh2(float a, float b) {
    __half2 h = __floats2half2_rn(a, b); return *reinterpret_cast<unsigned*>(&h);
}
__device__ __forceinline__ float wredsum(float v) {
    #pragma unroll
    for (int o = 16; o; o >>= 1) v += __shfl_xor_sync(0xffffffffu, v, o);
    return v;
}
__device__ __forceinline__ float wredmax(float v) {
    #pragma unroll
    for (int o = 16; o; o >>= 1) v = fmaxf(v, __shfl_xor_sync(0xffffffffu, v, o));
    return v;
}

// ---------------- reset sync (runs each replay) ----------------
__global__ void k_init_sync() {
    if (blockIdx.x == 0 && threadIdx.x == 0) g_arrive = 0;
}

// ---------------- weight prep: packed fp16 quad layouts ----------------
__global__ void k_prep(const float* __restrict__ W_ih, const float* __restrict__ W_hh,
                       const float* __restrict__ b_ih, const float* __restrict__ b_hh,
                       const float* __restrict__ w2,   const float* __restrict__ lin_w,
                       const float* __restrict__ emb) {
    int gt = blockIdx.x * blockDim.x + threadIdx.x;
    int stride = gridDim.x * blockDim.x;
    for (int i = gt; i < 50 * GATES; i += stride) {
        int u = i / GATES, r = i % GATES;
        const float* p = &W_ih[r * 300 + 4 * u];
        g_WcQ[i] = make_uint2(packh2(p[0], p[1]), packh2(p[2], p[3]));
    }
    for (int i = gt; i < 25 * GATES; i += stride) {
        int u = i / GATES, r = i % GATES;
        const float* p = &W_hh[r * ST + 4 * u];
        g_WhQ[i] = make_uint2(packh2(p[0], p[1]), packh2(p[2], p[3]));
    }
    for (int i = gt; i < 50 * ATTD; i += stride) {
        int u = i / ATTD, j = i % ATTD;
        const float* p = &w2[j * ST2 + 4 * u];
        g_w2Q[i] = make_uint2(packh2(p[0], p[1]), packh2(p[2], p[3]));
    }
    for (int i = gt; i < 25 * VOCABD; i += stride) {
        int u = i / VOCABD, v = i % VOCABD;
        const float* p = &lin_w[v * ST + 4 * u];
        g_linQ[i] = make_uint2(packh2(p[0], p[1]), packh2(p[2], p[3]));
    }
    for (int i = gt; i < VOCABD * GATES; i += stride) {
        int v = i % VOCABD, r = i / VOCABD;
        float a = b_ih[r] + b_hh[r];
        const float* wrow = &W_ih[r * 300 + 200];
        const float* erow = &emb[v * EMBD];
        #pragma unroll 4
        for (int e = 0; e < EMBD; e++) a = fmaf(wrow[e], erow[e], a);
        g_embproj[v * GATES + r] = a;
    }
}

// ---------------- encoder precompute: w1dt (transposed fp16) + input^T -------
__global__ __launch_bounds__(256, 1)
void k_enc(const float* __restrict__ inp, const float* __restrict__ w1) {
    extern __shared__ char smraw[];
    float2* w1s   = (float2*)smraw;                 // [k][j2] : 200*50 float2 = 80000 B
    __half* stage = (__half*)(smraw + 80000);       // [256][210] halfs = 107520 B
    const int tid = threadIdx.x;
    const int l0  = blockIdx.x * 256;
    const int l   = l0 + tid;

    for (int idx = tid; idx < ST2 * 50; idx += 256) {
        int k = idx / 50, j2 = idx % 50;
        w1s[idx] = make_float2(w1[(2 * j2) * ST2 + k], w1[(2 * j2 + 1) * ST2 + k]);
    }
    __syncthreads();

    float2 acc[50];
    #pragma unroll
    for (int j2 = 0; j2 < 50; j2++) acc[j2] = make_float2(0.f, 0.f);

    for (int k = 0; k < ST2; k++) {
        float x = inp[(size_t)k * LDIM + l];        // coalesced
        stage[tid * 210 + k] = __float2half(x);
        const float2* wr = &w1s[k * 50];
        #pragma unroll
        for (int j2 = 0; j2 < 50; j2++) {
            float2 w = wr[j2];
            acc[j2].x = fmaf(w.x, x, acc[j2].x);
            acc[j2].y = fmaf(w.y, x, acc[j2].y);
        }
    }
    __syncthreads();

    // coalesced half2 write of transposed input: g_inT2[l][q] = (in[2q][l], in[2q+1][l])
    for (int idx = tid; idx < 256 * 100; idx += 256) {
        int r = idx / 100, q = idx % 100;
        g_inT2[(size_t)(l0 + r) * 100 + q] = *(__half2*)(stage + r * 210 + 2 * q);
    }
    #pragma unroll
    for (int j2 = 0; j2 < 50; j2++)
        g_w1dtT2[(size_t)j2 * LDIM + l] = __floats2half2_rn(acc[j2].x, acc[j2].y);
}

// ---------------- persistent decoder ----------------
__global__ __launch_bounds__(512, 1)
void k_dec(const int* __restrict__ out_ids, const float* __restrict__ v_w,
           const float* __restrict__ v_b,   const float* __restrict__ lin_b,
           const int* __restrict__ eos_p,   float* __restrict__ out, int nb) {
    extern __shared__ uint2 dynsm[];
    uint2* sWc = dynsm;                  // 50*400 uint2 = 160000 B
    uint2* sW2 = dynsm + 50 * GATES;     // 50*100 uint2 = 40000 B

    __shared__ float  sscores[CHMAX];
    __shared__ float4 sx4[50];
    __shared__ float4 shc4[50];
    __shared__ float4 s_w2v[50];
    __shared__ float2 sP[4][ATTD];
    __shared__ float  sgates[GATES];
    __shared__ float  sh_[ST], sc_[ST];
    __shared__ float  sw2dt[ATTD];
    __shared__ float  svv[ATTD];
    __shared__ float  sred[33];
    __shared__ float  slog[VOCABD];
    __shared__ float  sS[2];

    const int b = blockIdx.x, tid = threadIdx.x;
    const int lane = tid & 31, wid = tid >> 5;
    const int chunk = (LDIM + nb - 1) / nb;
    const int l0 = b * chunk;
    int nl = LDIM - l0; if (nl > chunk) nl = chunk; if (nl < 0) nl = 0;

    for (int i = tid; i < 50 * GATES; i += 512) sWc[i] = g_WcQ[i];
    for (int i = tid; i < 50 * ATTD;  i += 512) sW2[i] = g_w2Q[i];
    if (tid < ATTD) svv[tid] = v_w[tid];
    __syncthreads();

    // exp shift constant C = v_b - (Sum|v| + |v_b|)  =>  p = exp(score_noVb + C) <= 1
    {
        float bb = (tid < ATTD) ? fabsf(svv[tid]) : 0.f;
        bb = wredsum(bb);
        if (lane == 0) sred[wid] = bb;
        __syncthreads();
        if (tid == 0) {
            float s = 0.f;
            #pragma unroll
            for (int i = 0; i < 16; i++) s += sred[i];
            float vb = v_b[0];
            sS[1] = vb - (s + fabsf(vb));
        }
        __syncthreads();
    }
    const float expC = sS[1];
    const int eosv = eos_p[0];
    int lastid = eosv;

    // ---- priming step (redundant in every block) ----
    if (tid < GATES) sgates[tid] = g_embproj[eosv * GATES + tid];
    __syncthreads();
    if (tid < ST) {
        float gi = sigmoidf_(sgates[tid]);
        float gg = tanhf(sgates[2 * ST + tid]);
        float go = sigmoidf_(sgates[3 * ST + tid]);
        float c = gi * gg;
        float h = go * tanhf(c);
        sh_[tid] = h; sc_[tid] = c;
    }
    __syncthreads();
    if (tid < 50) {
        int u = tid;
        const float* src = (u < 25) ? &sh_[4 * u] : &sc_[4 * (u - 25)];
        shc4[u] = make_float4(src[0], src[1], src[2], src[3]);
    }
    __syncthreads();
    // w2dt + pack s_w2v
    {
        const int part = tid / 100, j = tid - part * 100;
        if (tid < 400) {
            float a = 0.f;
            #pragma unroll 5
            for (int u = part; u < 50; u += 4) {
                uint2 w = sW2[u * ATTD + j];
                float4 x = shc4[u];
                float2 f0 = __half22float2(u2h2(w.x)), f1 = __half22float2(u2h2(w.y));
                a = fmaf(f0.x, x.x, a); a = fmaf(f0.y, x.y, a);
                a = fmaf(f1.x, x.z, a); a = fmaf(f1.y, x.w, a);
            }
            sP[part][j].x = a;
        }
        __syncthreads();
        if (tid < ATTD) sw2dt[tid] = sP[0][tid].x + sP[1][tid].x + sP[2][tid].x + sP[3][tid].x;
        __syncthreads();
        if (tid < 50) s_w2v[tid] = make_float4(sw2dt[2 * tid], sw2dt[2 * tid + 1],
                                               svv[2 * tid],   svv[2 * tid + 1]);
        __syncthreads();
    }

    // ================= main decode loop =================
    for (int t = 0; t < TSTEPS; t++) {
        const int par = t & 1;

        // ---- pass A: scores -> p = exp(score - bound), per-l, fully coalesced ----
        float ssum = 0.f;
        for (int li = tid; li < nl; li += 512) {
            const size_t l = (size_t)(l0 + li);
            float sc = 0.f;
            #pragma unroll 10
            for (int j2 = 0; j2 < 50; j2++) {
                float2 wf = __half22float2(__ldcg(&g_w1dtT2[(size_t)j2 * LDIM + l]));
                float4 wv = s_w2v[j2];
                sc += tanh_fast(wf.x + wv.x) * wv.z + tanh_fast(wf.y + wv.y) * wv.w;
            }
            float p = __expf(sc + expC);
            sscores[li] = p;
            ssum += p;
        }
        ssum = wredsum(ssum);
        if (lane == 0) sred[wid] = ssum;
        __syncthreads();
        if (tid == 0) {
            float s = 0.f;
            #pragma unroll
            for (int i = 0; i < 16; i++) s += sred[i];
            g_s[par][b] = s;
        }
        __syncthreads();

        // ---- pass B: partial ctx over this chunk (4 l-segments x 100 k-pairs) ----
        {
            const int seg = tid / 100, q = tid - seg * 100;
            if (tid < 400) {
                int seglen = (nl + 3) >> 2;
                int ls = seg * seglen, le = ls + seglen;
                if (le > nl) le = nl;
                if (ls > nl) ls = nl;
                float2 acc = make_float2(0.f, 0.f);
                const __half2* base = g_inT2 + (size_t)l0 * 100 + q;
                #pragma unroll 8
                for (int li = ls; li < le; li++) {
                    float p = sscores[li];
                    float2 f = __half22float2(__ldcg(&base[(size_t)li * 100]));
                    acc.x = fmaf(p, f.x, acc.x);
                    acc.y = fmaf(p, f.y, acc.y);
                }
                sP[seg][q] = acc;
            }
        }
        __syncthreads();
        if (tid < ATTD) {
            float2 a0 = sP[0][tid], a1 = sP[1][tid], a2 = sP[2][tid], a3 = sP[3][tid];
            g_ctx[par][b * ATTD + tid] = make_float2((a0.x + a1.x) + (a2.x + a3.x),
                                                     (a0.y + a1.y) + (a2.y + a3.y));
        }
        __threadfence();
        __syncthreads();

        // ---- single global barrier per step ----
        if (tid == 0) {
            atomicAdd(&g_arrive, 1);
            const int target = nb * (t + 1);
            while (*(volatile int*)&g_arrive < target) __nanosleep(64);
            __threadfence();
        }
        __syncthreads();

        // ---- merge partials (every block, high-MLP) ----
        {
            const int sub = tid / 100, q = tid - sub * 100;
            if (tid < 400) {
                float2 acc = make_float2(0.f, 0.f);
                const float2* cp = &g_ctx[par][0];
                #pragma unroll 8
                for (int i = sub; i < nb; i += 4) {
                    float2 v = __ldcg(&cp[i * ATTD + q]);
                    acc.x += v.x; acc.y += v.y;
                }
                sP[sub][q] = acc;
            }
        }
        __syncthreads();
        {
            float sv_ = (tid < nb) ? __ldcg(&g_s[par][tid]) : 0.f;
            sv_ = wredsum(sv_);
            if (lane == 0) sred[wid] = sv_;
            __syncthreads();
            if (tid == 0) {
                float s = 0.f;
                #pragma unroll
                for (int i = 0; i < 16; i++) s += sred[i];
                sS[0] = 1.f / s;
            }
        }
        __syncthreads();
        if (tid < ATTD) {
            const float Sinv = sS[0];
            float2 a0 = sP[0][tid], a1 = sP[1][tid], a2 = sP[2][tid], a3 = sP[3][tid];
            float2 r = make_float2(((a0.x + a1.x) + (a2.x + a3.x)) * Sinv,
                                   ((a0.y + a1.y) + (a2.y + a3.y)) * Sinv);
            ((float2*)sx4)[tid] = r;
        }
        __syncthreads();

        // ---- gates (redundant): embproj + Wc@ctx (smem) + Wh@h (L2) ----
        if (tid < GATES) {
            float a = g_embproj[lastid * GATES + tid];
            #pragma unroll 5
            for (int u = 0; u < 50; u++) {
                uint2 w = sWc[u * GATES + tid];
                float4 x = sx4[u];
                float2 f0 = __half22float2(u2h2(w.x)), f1 = __half22float2(u2h2(w.y));
                a = fmaf(f0.x, x.x, a); a = fmaf(f0.y, x.y, a);
                a = fmaf(f1.x, x.z, a); a = fmaf(f1.y, x.w, a);
            }
            #pragma unroll 5
            for (int u = 0; u < 25; u++) {
                uint2 w = __ldcg(&g_WhQ[u * GATES + tid]);
                float4 x = shc4[u];               // h quads (prev step)
                float2 f0 = __half22float2(u2h2(w.x)), f1 = __half22float2(u2h2(w.y));
                a = fmaf(f0.x, x.x, a); a = fmaf(f0.y, x.y, a);
                a = fmaf(f1.x, x.z, a); a = fmaf(f1.y, x.w, a);
            }
            sgates[tid] = a;
        }
        __syncthreads();
        if (tid < ST) {
            float gi = sigmoidf_(sgates[tid]);
            float gf = sigmoidf_(sgates[ST + tid]);
            float gg = tanhf(sgates[2 * ST + tid]);
            float go = sigmoidf_(sgates[3 * ST + tid]);
            float c = fmaf(gf, sc_[tid], gi * gg);
            float h = go * tanhf(c);
            sh_[tid] = h; sc_[tid] = c;
            if (b == 0) g_h[t][tid] = h;
        }
        __syncthreads();
        if (tid < 50) {
            int u = tid;
            const float* src = (u < 25) ? &sh_[4 * u] : &sc_[4 * (u - 25)];
            shc4[u] = make_float4(src[0], src[1], src[2], src[3]);
        }
        __syncthreads();
        // w2dt for next step + repack s_w2v
        {
            const int part = tid / 100, j = tid - part * 100;
            if (tid < 400) {
                float a = 0.f;
                #pragma unroll 5
                for (int u = part; u < 50; u += 4) {
                    uint2 w = sW2[u * ATTD + j];
                    float4 x = shc4[u];
                    float2 f0 = __half22float2(u2h2(w.x)), f1 = __half22float2(u2h2(w.y));
                    a = fmaf(f0.x, x.x, a); a = fmaf(f0.y, x.y, a);
                    a = fmaf(f1.x, x.z, a); a = fmaf(f1.y, x.w, a);
                }
                sP[part][j].x = a;
            }
            __syncthreads();
            if (tid < ATTD) sw2dt[tid] = sP[0][tid].x + sP[1][tid].x + sP[2][tid].x + sP[3][tid].x;
            __syncthreads();
            if (tid < 50) s_w2v[tid] = make_float4(sw2dt[2 * tid], sw2dt[2 * tid + 1],
                                                   svv[2 * tid],   svv[2 * tid + 1]);
        }
        lastid = out_ids[t];
        __syncthreads();
    }

    // ---- make block-0's g_h writes globally visible, then barrier ----
    __threadfence();
    __syncthreads();
    if (tid == 0) {
        atomicAdd(&g_arrive, 1);
        while (*(volatile int*)&g_arrive < nb * (TSTEPS + 1)) __nanosleep(64);
        __threadfence();
    }
    __syncthreads();

    // ---- deferred losses: steps distributed across blocks ----
    float myloss = 0.f;
    for (int t = b; t < TSTEPS; t += nb) {
        if (tid < 25) {
            const float* hp = &g_h[t][4 * tid];
            shc4[tid] = make_float4(hp[0], hp[1], hp[2], hp[3]);
        }
        __syncthreads();
        if (tid < VOCABD) {
            float a = lin_b[tid];
            #pragma unroll
            for (int u = 0; u < 25; u++) {
                uint2 w = __ldcg(&g_linQ[u * VOCABD + tid]);
                float4 x = shc4[u];
                float2 f0 = __half22float2(u2h2(w.x)), f1 = __half22float2(u2h2(w.y));
                a = fmaf(f0.x, x.x, a); a = fmaf(f0.y, x.y, a);
                a = fmaf(f1.x, x.z, a); a = fmaf(f1.y, x.w, a);
            }
            slog[tid] = a;
            float m = wredmax(a);
            if (lane == 0) sred[wid] = m;
        }
        __syncthreads();
        if (tid == 0)
            sred[32] = fmaxf(fmaxf(sred[0], sred[1]), fmaxf(sred[2], sred[3]));
        __syncthreads();
        const float M = sred[32];
        if (tid < VOCABD) {
            float e = __expf(slog[tid] - M);
            e = wredsum(e);
            if (lane == 0) sred[16 + wid] = e;
        }
        __syncthreads();
        if (tid == 0) {
            float S2 = sred[16] + sred[17] + sred[18] + sred[19];
            int ch = out_ids[t];
            myloss += (M + logf(S2)) - slog[ch];
        }
        __syncthreads();
    }
    if (tid == 0) g_losspart[b] = myloss;
    __threadfence();
    __syncthreads();
    if (tid == 0) atomicAdd(&g_arrive, 1);
    if (b == 0) {
        if (tid == 0) {
            while (*(volatile int*)&g_arrive < nb * (TSTEPS + 2)) __nanosleep(64);
            __threadfence();
        }
        __syncthreads();
        float v = (tid < nb) ? g_losspart[tid] : 0.f;
        v = wredsum(v);
        if (lane == 0) sred[wid] = v;
        __syncthreads();
        if (tid == 0) {
            float s = 0.f;
            #pragma unroll
            for (int i = 0; i < 16; i++) s += sred[i];
            out[0] = s;
        }
    }
}

// ---------------- launch ----------------
extern "C" void kernel_launch(void* const* d_in, const int* in_sizes, int n_in,
                              void* d_out, int out_size) {
    const float* input_mat = (const float*)d_in[0];
    const int*   out_ids   = (const int*)  d_in[1];
    const float* W_ih      = (const float*)d_in[2];
    const float* W_hh      = (const float*)d_in[3];
    const float* b_ih      = (const float*)d_in[4];
    const float* b_hh      = (const float*)d_in[5];
    const float* w1        = (const float*)d_in[6];
    const float* w2        = (const float*)d_in[7];
    const float* v_w       = (const float*)d_in[8];
    const float* v_b       = (const float*)d_in[9];
    const float* lin_w     = (const float*)d_in[10];
    const float* lin_b     = (const float*)d_in[11];
    const float* emb       = (const float*)d_in[12];
    const int*   eos_id    = (const int*)  d_in[13];
    float* out = (float*)d_out;

    int nb = 148;
    cudaDeviceGetAttribute(&nb, cudaDevAttrMultiProcessorCount, 0);
    if (nb > MAXNB) nb = MAXNB;

    cudaFuncSetAttribute(k_enc, cudaFuncAttributeMaxDynamicSharedMemorySize, 187520);
    cudaFuncSetAttribute(k_dec, cudaFuncAttributeMaxDynamicSharedMemorySize, 200000);

    k_init_sync<<<1, 32>>>();
    k_prep<<<120, 256>>>(W_ih, W_hh, b_ih, b_hh, w2, lin_w, emb);
    k_enc<<<LDIM / 256, 256, 187520>>>(input_mat, w1);
    k_dec<<<nb, 512, 200000>>>(out_ids, v_w, v_b, lin_b, eos_id, out, nb);
}